// round 4
// baseline (speedup 1.0000x reference)
#include <cuda_runtime.h>

// PLE layers: 3 expert stacks (a, b, share), 8 experts each, dense softmax gating.
//   ea/eb/es[b,e,:] = x_σ[b,:] @ W_σ[e] + b_σ[e]      (B=16384, IN=256, D=128)
//   out_a = Σ wA[b,e]·ea + Σ wA[b,8+e]·es   (wA = softmax(x_a @ Ga^T), 16 gates)
//   out_b analogous; out_s over [ea,eb,es] with 24 gates.
// Fully fused single kernel: gates+softmax in smem, expert GEMMs via tf32
// mma.sync m16n8k8 folded directly into register output accumulators.

#define BT      16384
#define IN_D    256
#define EXP_D   128
#define NE      8
#define TB      64          // batch rows per CTA
#define KC      32          // K chunk for W streaming
#define XSS     260         // x smem stride (words): bank = 4*gid+tig, conflict-free
#define WSS     136         // w smem stride (words): bank = 8*tig+gid, conflict-free
#define GSS     57          // gate-weight smem stride (odd -> conflict-free row reads)
#define NTHREADS 256

__device__ __forceinline__ unsigned f2tf(float f) {
    unsigned u;
    asm("cvt.rna.tf32.f32 %0, %1;" : "=r"(u) : "f"(f));
    return u;
}

__device__ __forceinline__ void mma8(float& c0, float& c1, float& c2, float& c3,
                                     unsigned a0, unsigned a1, unsigned a2, unsigned a3,
                                     unsigned b0, unsigned b1) {
    asm volatile(
        "mma.sync.aligned.m16n8k8.row.col.f32.tf32.tf32.f32 "
        "{%0,%1,%2,%3}, {%4,%5,%6,%7}, {%8,%9}, {%0,%1,%2,%3};\n"
        : "+f"(c0), "+f"(c1), "+f"(c2), "+f"(c3)
        : "r"(a0), "r"(a1), "r"(a2), "r"(a3), "r"(b0), "r"(b1));
}

__global__ __launch_bounds__(NTHREADS, 1)
void ple_kernel(const float* __restrict__ xa, const float* __restrict__ xb,
                const float* __restrict__ xsh,
                const float* __restrict__ Wa, const float* __restrict__ ba,
                const float* __restrict__ Wb, const float* __restrict__ bb,
                const float* __restrict__ Wsx, const float* __restrict__ bsx,
                const float* __restrict__ Ga, const float* __restrict__ Gb,
                const float* __restrict__ Gq,
                float* __restrict__ out)
{
    extern __shared__ float smem[];
    float* xs  = smem;                 // TB*XSS : x tile (tf32 bits)
    float* ws  = xs + TB * XSS;        // KC*WSS : W chunk (tf32 bits)
    float* wsm = ws + KC * WSS;        // TB*GSS : gate weights [r][0:16 wA,16:32 wB,32:56 wS]
    float* bsm = wsm + TB * GSS;       // 3*1024 : biases [stack][e*128+d]

    const int tid  = threadIdx.x;
    const int lane = tid & 31;
    const int wid  = tid >> 5;
    const int gid  = lane >> 2;        // groupID (0..7)
    const int tig  = lane & 3;         // threadID-in-group (0..3)
    const int wm   = wid >> 2;         // warp row (0..1): 32 rows each
    const int wn   = wid & 3;          // warp col (0..3): 32 cols each
    const int row0 = blockIdx.x * TB;

    // biases -> smem
    for (int i = tid; i < 1024; i += NTHREADS) {
        bsm[i]        = ba[i];
        bsm[1024 + i] = bb[i];
        bsm[2048 + i] = bsx[i];
    }

    // ---------------- Phase 1: gate logits + softmax (full fp32) ----------------
    #pragma unroll
    for (int sg = 0; sg < 3; ++sg) {
        const float* X = (sg == 0) ? xa : (sg == 1) ? xb : xsh;
        const float* G = (sg == 0) ? Ga : (sg == 1) ? Gb : Gq;
        const int NG   = (sg == 2) ? 24 : 16;
        const int WOFF = sg * 16;      // 0 / 16 / 32

        __syncthreads();   // xs reuse + prev softmax writes
        const float4* src = (const float4*)(X + (size_t)row0 * IN_D);
        for (int idx = tid; idx < TB * IN_D / 4; idx += NTHREADS) {
            int r = idx >> 6, k4 = (idx & 63) << 2;
            float4 v = __ldg(src + idx);
            uint4 u;
            u.x = f2tf(v.x); u.y = f2tf(v.y); u.z = f2tf(v.z); u.w = f2tf(v.w);
            *(uint4*)(xs + r * XSS + k4) = u;
        }
        __syncthreads();

        for (int idx = tid; idx < TB * NG; idx += NTHREADS) {
            int r = idx / NG, g = idx - r * NG;
            const float4* xp = (const float4*)(xs + r * XSS);
            const float4* gp = (const float4*)(G + g * IN_D);
            float acc = 0.f;
            #pragma unroll 8
            for (int k = 0; k < IN_D / 4; ++k) {
                float4 xv = xp[k];
                float4 gv = __ldg(gp + k);
                acc += xv.x * gv.x; acc += xv.y * gv.y;
                acc += xv.z * gv.z; acc += xv.w * gv.w;
            }
            wsm[r * GSS + WOFF + g] = acc;
        }
        __syncthreads();

        if (tid < TB) {
            float* wr = wsm + tid * GSS + WOFF;
            float m = wr[0];
            for (int g = 1; g < NG; ++g) m = fmaxf(m, wr[g]);
            float s = 0.f;
            for (int g = 0; g < NG; ++g) { float e = expf(wr[g] - m); wr[g] = e; s += e; }
            float inv = 1.f / s;
            for (int g = 0; g < NG; ++g) wr[g] *= inv;
        }
    }

    // ---------------- Phase 2: expert GEMMs + gated fold ----------------
    float oa[2][4][4] = {}, ob[2][4][4] = {}, os[2][4][4] = {};

    #pragma unroll
    for (int sg = 0; sg < 3; ++sg) {
        const float* X = (sg == 0) ? xa : (sg == 1) ? xb : xsh;
        const float* W = (sg == 0) ? Wa : (sg == 1) ? Wb : Wsx;

        __syncthreads();   // all prior xs/wsm readers done
        const float4* src = (const float4*)(X + (size_t)row0 * IN_D);
        for (int idx = tid; idx < TB * IN_D / 4; idx += NTHREADS) {
            int r = idx >> 6, k4 = (idx & 63) << 2;
            float4 v = __ldg(src + idx);
            uint4 u;
            u.x = f2tf(v.x); u.y = f2tf(v.y); u.z = f2tf(v.z); u.w = f2tf(v.w);
            *(uint4*)(xs + r * XSS + k4) = u;
        }
        __syncthreads();

        for (int e = 0; e < NE; ++e) {
            float ec[2][4][4] = {};
            const float* We = W + e * IN_D * EXP_D;

            float4 rbuf[4];
            {
                const float4* s4 = (const float4*)We;
                #pragma unroll
                for (int j = 0; j < 4; ++j) rbuf[j] = __ldg(s4 + tid + j * NTHREADS);
            }

            for (int c = 0; c < IN_D / KC; ++c) {
                // stage chunk c (tf32-converted) into smem
                #pragma unroll
                for (int j = 0; j < 4; ++j) {
                    int idx = tid + j * NTHREADS;
                    int r = idx >> 5, c4 = (idx & 31) << 2;
                    uint4 u;
                    u.x = f2tf(rbuf[j].x); u.y = f2tf(rbuf[j].y);
                    u.z = f2tf(rbuf[j].z); u.w = f2tf(rbuf[j].w);
                    *(uint4*)(ws + r * WSS + c4) = u;
                }
                __syncthreads();

                // prefetch chunk c+1 (overlaps MMA below)
                if (c + 1 < IN_D / KC) {
                    const float4* s4 = (const float4*)(We + (c + 1) * KC * EXP_D);
                    #pragma unroll
                    for (int j = 0; j < 4; ++j) rbuf[j] = __ldg(s4 + tid + j * NTHREADS);
                }

                #pragma unroll
                for (int kk = 0; kk < KC / 8; ++kk) {
                    unsigned a0[2], a1[2], a2[2], a3[2];
                    #pragma unroll
                    for (int mt = 0; mt < 2; ++mt) {
                        const float* xr = xs + (wm * 32 + mt * 16 + gid) * XSS + c * KC + kk * 8;
                        a0[mt] = __float_as_uint(xr[tig]);
                        a1[mt] = __float_as_uint(xr[8 * XSS + tig]);
                        a2[mt] = __float_as_uint(xr[tig + 4]);
                        a3[mt] = __float_as_uint(xr[8 * XSS + tig + 4]);
                    }
                    #pragma unroll
                    for (int nt = 0; nt < 4; ++nt) {
                        int n = wn * 32 + nt * 8 + gid;
                        unsigned b0 = __float_as_uint(ws[(kk * 8 + tig) * WSS + n]);
                        unsigned b1 = __float_as_uint(ws[(kk * 8 + tig + 4) * WSS + n]);
                        #pragma unroll
                        for (int mt = 0; mt < 2; ++mt)
                            mma8(ec[mt][nt][0], ec[mt][nt][1], ec[mt][nt][2], ec[mt][nt][3],
                                 a0[mt], a1[mt], a2[mt], a3[mt], b0, b1);
                    }
                }
                __syncthreads();
            }

            // fold expert tile into gated output accumulators
            #pragma unroll
            for (int mt = 0; mt < 2; ++mt) {
                int rl = wm * 32 + mt * 16 + gid;
                float w1l = 0.f, w1h = 0.f, w2l = 0.f, w2h = 0.f, w3l = 0.f, w3h = 0.f;
                if (sg == 0) {
                    w1l = wsm[rl * GSS + e];        w1h = wsm[(rl + 8) * GSS + e];        // wA[e]  -> out_a
                    w2l = wsm[rl * GSS + 32 + e];   w2h = wsm[(rl + 8) * GSS + 32 + e];   // wS[e]  -> out_s
                } else if (sg == 1) {
                    w1l = wsm[rl * GSS + 16 + e];   w1h = wsm[(rl + 8) * GSS + 16 + e];   // wB[e]  -> out_b
                    w2l = wsm[rl * GSS + 40 + e];   w2h = wsm[(rl + 8) * GSS + 40 + e];   // wS[8+e]-> out_s
                } else {
                    w1l = wsm[rl * GSS + 8 + e];    w1h = wsm[(rl + 8) * GSS + 8 + e];    // wA[8+e]-> out_a
                    w2l = wsm[rl * GSS + 24 + e];   w2h = wsm[(rl + 8) * GSS + 24 + e];   // wB[8+e]-> out_b
                    w3l = wsm[rl * GSS + 48 + e];   w3h = wsm[(rl + 8) * GSS + 48 + e];   // wS[16+e]->out_s
                }
                #pragma unroll
                for (int nt = 0; nt < 4; ++nt) {
                    int c0 = wn * 32 + nt * 8 + 2 * tig;
                    const float* bp = bsm + sg * 1024 + e * EXP_D + c0;
                    float t0 = ec[mt][nt][0] + bp[0];
                    float t1 = ec[mt][nt][1] + bp[1];
                    float t2 = ec[mt][nt][2] + bp[0];
                    float t3 = ec[mt][nt][3] + bp[1];
                    if (sg == 0) {
                        oa[mt][nt][0] += w1l * t0; oa[mt][nt][1] += w1l * t1;
                        oa[mt][nt][2] += w1h * t2; oa[mt][nt][3] += w1h * t3;
                        os[mt][nt][0] += w2l * t0; os[mt][nt][1] += w2l * t1;
                        os[mt][nt][2] += w2h * t2; os[mt][nt][3] += w2h * t3;
                    } else if (sg == 1) {
                        ob[mt][nt][0] += w1l * t0; ob[mt][nt][1] += w1l * t1;
                        ob[mt][nt][2] += w1h * t2; ob[mt][nt][3] += w1h * t3;
                        os[mt][nt][0] += w2l * t0; os[mt][nt][1] += w2l * t1;
                        os[mt][nt][2] += w2h * t2; os[mt][nt][3] += w2h * t3;
                    } else {
                        oa[mt][nt][0] += w1l * t0; oa[mt][nt][1] += w1l * t1;
                        oa[mt][nt][2] += w1h * t2; oa[mt][nt][3] += w1h * t3;
                        ob[mt][nt][0] += w2l * t0; ob[mt][nt][1] += w2l * t1;
                        ob[mt][nt][2] += w2h * t2; ob[mt][nt][3] += w2h * t3;
                        os[mt][nt][0] += w3l * t0; os[mt][nt][1] += w3l * t1;
                        os[mt][nt][2] += w3h * t2; os[mt][nt][3] += w3h * t3;
                    }
                }
            }
        }
    }

    // ---------------- write out: [out_a | out_b | out_s], each [B,128] ----------------
    const size_t OS = (size_t)BT * EXP_D;
    #pragma unroll
    for (int mt = 0; mt < 2; ++mt) {
        int r = row0 + wm * 32 + mt * 16 + gid;
        #pragma unroll
        for (int nt = 0; nt < 4; ++nt) {
            int c0 = wn * 32 + nt * 8 + 2 * tig;
            size_t p0 = (size_t)r * EXP_D + c0;
            size_t p1 = (size_t)(r + 8) * EXP_D + c0;
            *(float2*)(out + p0)          = make_float2(oa[mt][nt][0], oa[mt][nt][1]);
            *(float2*)(out + p1)          = make_float2(oa[mt][nt][2], oa[mt][nt][3]);
            *(float2*)(out + OS + p0)     = make_float2(ob[mt][nt][0], ob[mt][nt][1]);
            *(float2*)(out + OS + p1)     = make_float2(ob[mt][nt][2], ob[mt][nt][3]);
            *(float2*)(out + 2 * OS + p0) = make_float2(os[mt][nt][0], os[mt][nt][1]);
            *(float2*)(out + 2 * OS + p1) = make_float2(os[mt][nt][2], os[mt][nt][3]);
        }
    }
}

extern "C" void kernel_launch(void* const* d_in, const int* in_sizes, int n_in,
                              void* d_out, int out_size) {
    (void)in_sizes; (void)n_in; (void)out_size;
    constexpr int SMEM_BYTES = (TB * XSS + KC * WSS + TB * GSS + 3 * 1024) * 4;  // ~110.8 KB
    cudaFuncSetAttribute(ple_kernel, cudaFuncAttributeMaxDynamicSharedMemorySize, SMEM_BYTES);
    ple_kernel<<<BT / TB, NTHREADS, SMEM_BYTES>>>(
        (const float*)d_in[0], (const float*)d_in[1], (const float*)d_in[2],
        (const float*)d_in[3], (const float*)d_in[4],
        (const float*)d_in[5], (const float*)d_in[6],
        (const float*)d_in[7], (const float*)d_in[8],
        (const float*)d_in[9], (const float*)d_in[10], (const float*)d_in[11],
        (float*)d_out);
}

// round 5
// speedup vs baseline: 1.0014x; 1.0014x over previous
#include <cuda_runtime.h>

// PLE layers: 3 expert stacks (a, b, share), 8 experts each, dense softmax gating.
//   ea/eb/es[b,e,:] = x_σ[b,:] @ W_σ[e] + b_σ[e]      (B=16384, IN=256, D=128)
//   out_a = Σ wA[b,e]·ea + Σ wA[b,8+e]·es   (wA = softmax(x_a @ Ga^T), 16 gates)
//   out_b analogous; out_s over [ea,eb,es] with 24 gates.
// Fully fused single kernel: gates+softmax in smem, expert GEMMs via tf32
// mma.sync m16n8k8 folded directly into register output accumulators.

#define BT      16384
#define IN_D    256
#define EXP_D   128
#define NE      8
#define TB      64          // batch rows per CTA
#define KC      32          // K chunk for W streaming
#define XSS     260         // x smem stride (words): bank = 4*gid+tig, conflict-free
#define WSS     136         // w smem stride (words): bank = 8*tig+gid, conflict-free
#define GSS     57          // gate-weight smem stride (odd -> conflict-free row reads)
#define NTHREADS 256

__device__ __forceinline__ unsigned f2tf(float f) {
    unsigned u;
    asm("cvt.rna.tf32.f32 %0, %1;" : "=r"(u) : "f"(f));
    return u;
}

__device__ __forceinline__ void mma8(float& c0, float& c1, float& c2, float& c3,
                                     unsigned a0, unsigned a1, unsigned a2, unsigned a3,
                                     unsigned b0, unsigned b1) {
    asm volatile(
        "mma.sync.aligned.m16n8k8.row.col.f32.tf32.tf32.f32 "
        "{%0,%1,%2,%3}, {%4,%5,%6,%7}, {%8,%9}, {%0,%1,%2,%3};\n"
        : "+f"(c0), "+f"(c1), "+f"(c2), "+f"(c3)
        : "r"(a0), "r"(a1), "r"(a2), "r"(a3), "r"(b0), "r"(b1));
}

__global__ __launch_bounds__(NTHREADS, 1)
void ple_kernel(const float* __restrict__ xa, const float* __restrict__ xb,
                const float* __restrict__ xsh,
                const float* __restrict__ Wa, const float* __restrict__ ba,
                const float* __restrict__ Wb, const float* __restrict__ bb,
                const float* __restrict__ Wsx, const float* __restrict__ bsx,
                const float* __restrict__ Ga, const float* __restrict__ Gb,
                const float* __restrict__ Gq,
                float* __restrict__ out)
{
    extern __shared__ float smem[];
    float* xs  = smem;                 // TB*XSS : x tile (tf32 bits)
    float* ws  = xs + TB * XSS;        // KC*WSS : W chunk (tf32 bits)
    float* wsm = ws + KC * WSS;        // TB*GSS : gate weights [r][0:16 wA,16:32 wB,32:56 wS]
    float* bsm = wsm + TB * GSS;       // 3*1024 : biases [stack][e*128+d]

    const int tid  = threadIdx.x;
    const int lane = tid & 31;
    const int wid  = tid >> 5;
    const int gid  = lane >> 2;        // groupID (0..7)
    const int tig  = lane & 3;         // threadID-in-group (0..3)
    const int wm   = wid >> 2;         // warp row (0..1): 32 rows each
    const int wn   = wid & 3;          // warp col (0..3): 32 cols each
    const int row0 = blockIdx.x * TB;

    // biases -> smem
    for (int i = tid; i < 1024; i += NTHREADS) {
        bsm[i]        = ba[i];
        bsm[1024 + i] = bb[i];
        bsm[2048 + i] = bsx[i];
    }

    // ---------------- Phase 1: gate logits + softmax (full fp32) ----------------
    #pragma unroll
    for (int sg = 0; sg < 3; ++sg) {
        const float* X = (sg == 0) ? xa : (sg == 1) ? xb : xsh;
        const float* G = (sg == 0) ? Ga : (sg == 1) ? Gb : Gq;
        const int NG   = (sg == 2) ? 24 : 16;
        const int WOFF = sg * 16;      // 0 / 16 / 32

        __syncthreads();   // xs reuse + prev softmax writes
        const float4* src = (const float4*)(X + (size_t)row0 * IN_D);
        for (int idx = tid; idx < TB * IN_D / 4; idx += NTHREADS) {
            int r = idx >> 6, k4 = (idx & 63) << 2;
            float4 v = __ldg(src + idx);
            uint4 u;
            u.x = f2tf(v.x); u.y = f2tf(v.y); u.z = f2tf(v.z); u.w = f2tf(v.w);
            *(uint4*)(xs + r * XSS + k4) = u;
        }
        __syncthreads();

        for (int idx = tid; idx < TB * NG; idx += NTHREADS) {
            int r = idx / NG, g = idx - r * NG;
            const float4* xp = (const float4*)(xs + r * XSS);
            const float4* gp = (const float4*)(G + g * IN_D);
            float acc = 0.f;
            #pragma unroll 8
            for (int k = 0; k < IN_D / 4; ++k) {
                float4 xv = xp[k];
                float4 gv = __ldg(gp + k);
                acc += xv.x * gv.x; acc += xv.y * gv.y;
                acc += xv.z * gv.z; acc += xv.w * gv.w;
            }
            wsm[r * GSS + WOFF + g] = acc;
        }
        __syncthreads();

        if (tid < TB) {
            float* wr = wsm + tid * GSS + WOFF;
            float m = wr[0];
            for (int g = 1; g < NG; ++g) m = fmaxf(m, wr[g]);
            float s = 0.f;
            for (int g = 0; g < NG; ++g) { float e = expf(wr[g] - m); wr[g] = e; s += e; }
            float inv = 1.f / s;
            for (int g = 0; g < NG; ++g) wr[g] *= inv;
        }
    }

    // ---------------- Phase 2: expert GEMMs + gated fold ----------------
    float oa[2][4][4] = {}, ob[2][4][4] = {}, os[2][4][4] = {};

    #pragma unroll
    for (int sg = 0; sg < 3; ++sg) {
        const float* X = (sg == 0) ? xa : (sg == 1) ? xb : xsh;
        const float* W = (sg == 0) ? Wa : (sg == 1) ? Wb : Wsx;

        __syncthreads();   // all prior xs/wsm readers done
        const float4* src = (const float4*)(X + (size_t)row0 * IN_D);
        for (int idx = tid; idx < TB * IN_D / 4; idx += NTHREADS) {
            int r = idx >> 6, k4 = (idx & 63) << 2;
            float4 v = __ldg(src + idx);
            uint4 u;
            u.x = f2tf(v.x); u.y = f2tf(v.y); u.z = f2tf(v.z); u.w = f2tf(v.w);
            *(uint4*)(xs + r * XSS + k4) = u;
        }
        __syncthreads();

        for (int e = 0; e < NE; ++e) {
            float ec[2][4][4] = {};
            const float* We = W + e * IN_D * EXP_D;

            float4 rbuf[4];
            {
                const float4* s4 = (const float4*)We;
                #pragma unroll
                for (int j = 0; j < 4; ++j) rbuf[j] = __ldg(s4 + tid + j * NTHREADS);
            }

            for (int c = 0; c < IN_D / KC; ++c) {
                // stage chunk c (tf32-converted) into smem
                #pragma unroll
                for (int j = 0; j < 4; ++j) {
                    int idx = tid + j * NTHREADS;
                    int r = idx >> 5, c4 = (idx & 31) << 2;
                    uint4 u;
                    u.x = f2tf(rbuf[j].x); u.y = f2tf(rbuf[j].y);
                    u.z = f2tf(rbuf[j].z); u.w = f2tf(rbuf[j].w);
                    *(uint4*)(ws + r * WSS + c4) = u;
                }
                __syncthreads();

                // prefetch chunk c+1 (overlaps MMA below)
                if (c + 1 < IN_D / KC) {
                    const float4* s4 = (const float4*)(We + (c + 1) * KC * EXP_D);
                    #pragma unroll
                    for (int j = 0; j < 4; ++j) rbuf[j] = __ldg(s4 + tid + j * NTHREADS);
                }

                #pragma unroll
                for (int kk = 0; kk < KC / 8; ++kk) {
                    unsigned a0[2], a1[2], a2[2], a3[2];
                    #pragma unroll
                    for (int mt = 0; mt < 2; ++mt) {
                        const float* xr = xs + (wm * 32 + mt * 16 + gid) * XSS + c * KC + kk * 8;
                        a0[mt] = __float_as_uint(xr[tig]);
                        a1[mt] = __float_as_uint(xr[8 * XSS + tig]);
                        a2[mt] = __float_as_uint(xr[tig + 4]);
                        a3[mt] = __float_as_uint(xr[8 * XSS + tig + 4]);
                    }
                    #pragma unroll
                    for (int nt = 0; nt < 4; ++nt) {
                        int n = wn * 32 + nt * 8 + gid;
                        unsigned b0 = __float_as_uint(ws[(kk * 8 + tig) * WSS + n]);
                        unsigned b1 = __float_as_uint(ws[(kk * 8 + tig + 4) * WSS + n]);
                        #pragma unroll
                        for (int mt = 0; mt < 2; ++mt)
                            mma8(ec[mt][nt][0], ec[mt][nt][1], ec[mt][nt][2], ec[mt][nt][3],
                                 a0[mt], a1[mt], a2[mt], a3[mt], b0, b1);
                    }
                }
                __syncthreads();
            }

            // fold expert tile into gated output accumulators
            #pragma unroll
            for (int mt = 0; mt < 2; ++mt) {
                int rl = wm * 32 + mt * 16 + gid;
                float w1l = 0.f, w1h = 0.f, w2l = 0.f, w2h = 0.f, w3l = 0.f, w3h = 0.f;
                if (sg == 0) {
                    w1l = wsm[rl * GSS + e];        w1h = wsm[(rl + 8) * GSS + e];        // wA[e]  -> out_a
                    w2l = wsm[rl * GSS + 32 + e];   w2h = wsm[(rl + 8) * GSS + 32 + e];   // wS[e]  -> out_s
                } else if (sg == 1) {
                    w1l = wsm[rl * GSS + 16 + e];   w1h = wsm[(rl + 8) * GSS + 16 + e];   // wB[e]  -> out_b
                    w2l = wsm[rl * GSS + 40 + e];   w2h = wsm[(rl + 8) * GSS + 40 + e];   // wS[8+e]-> out_s
                } else {
                    w1l = wsm[rl * GSS + 8 + e];    w1h = wsm[(rl + 8) * GSS + 8 + e];    // wA[8+e]-> out_a
                    w2l = wsm[rl * GSS + 24 + e];   w2h = wsm[(rl + 8) * GSS + 24 + e];   // wB[8+e]-> out_b
                    w3l = wsm[rl * GSS + 48 + e];   w3h = wsm[(rl + 8) * GSS + 48 + e];   // wS[16+e]->out_s
                }
                #pragma unroll
                for (int nt = 0; nt < 4; ++nt) {
                    int c0 = wn * 32 + nt * 8 + 2 * tig;
                    const float* bp = bsm + sg * 1024 + e * EXP_D + c0;
                    float t0 = ec[mt][nt][0] + bp[0];
                    float t1 = ec[mt][nt][1] + bp[1];
                    float t2 = ec[mt][nt][2] + bp[0];
                    float t3 = ec[mt][nt][3] + bp[1];
                    if (sg == 0) {
                        oa[mt][nt][0] += w1l * t0; oa[mt][nt][1] += w1l * t1;
                        oa[mt][nt][2] += w1h * t2; oa[mt][nt][3] += w1h * t3;
                        os[mt][nt][0] += w2l * t0; os[mt][nt][1] += w2l * t1;
                        os[mt][nt][2] += w2h * t2; os[mt][nt][3] += w2h * t3;
                    } else if (sg == 1) {
                        ob[mt][nt][0] += w1l * t0; ob[mt][nt][1] += w1l * t1;
                        ob[mt][nt][2] += w1h * t2; ob[mt][nt][3] += w1h * t3;
                        os[mt][nt][0] += w2l * t0; os[mt][nt][1] += w2l * t1;
                        os[mt][nt][2] += w2h * t2; os[mt][nt][3] += w2h * t3;
                    } else {
                        oa[mt][nt][0] += w1l * t0; oa[mt][nt][1] += w1l * t1;
                        oa[mt][nt][2] += w1h * t2; oa[mt][nt][3] += w1h * t3;
                        ob[mt][nt][0] += w2l * t0; ob[mt][nt][1] += w2l * t1;
                        ob[mt][nt][2] += w2h * t2; ob[mt][nt][3] += w2h * t3;
                        os[mt][nt][0] += w3l * t0; os[mt][nt][1] += w3l * t1;
                        os[mt][nt][2] += w3h * t2; os[mt][nt][3] += w3h * t3;
                    }
                }
            }
        }
    }

    // ---------------- write out: [out_a | out_b | out_s], each [B,128] ----------------
    const size_t OS = (size_t)BT * EXP_D;
    #pragma unroll
    for (int mt = 0; mt < 2; ++mt) {
        int r = row0 + wm * 32 + mt * 16 + gid;
        #pragma unroll
        for (int nt = 0; nt < 4; ++nt) {
            int c0 = wn * 32 + nt * 8 + 2 * tig;
            size_t p0 = (size_t)r * EXP_D + c0;
            size_t p1 = (size_t)(r + 8) * EXP_D + c0;
            *(float2*)(out + p0)          = make_float2(oa[mt][nt][0], oa[mt][nt][1]);
            *(float2*)(out + p1)          = make_float2(oa[mt][nt][2], oa[mt][nt][3]);
            *(float2*)(out + OS + p0)     = make_float2(ob[mt][nt][0], ob[mt][nt][1]);
            *(float2*)(out + OS + p1)     = make_float2(ob[mt][nt][2], ob[mt][nt][3]);
            *(float2*)(out + 2 * OS + p0) = make_float2(os[mt][nt][0], os[mt][nt][1]);
            *(float2*)(out + 2 * OS + p1) = make_float2(os[mt][nt][2], os[mt][nt][3]);
        }
    }
}

extern "C" void kernel_launch(void* const* d_in, const int* in_sizes, int n_in,
                              void* d_out, int out_size) {
    (void)in_sizes; (void)n_in; (void)out_size;
    constexpr int SMEM_BYTES = (TB * XSS + KC * WSS + TB * GSS + 3 * 1024) * 4;  // ~110.8 KB
    cudaFuncSetAttribute(ple_kernel, cudaFuncAttributeMaxDynamicSharedMemorySize, SMEM_BYTES);
    ple_kernel<<<BT / TB, NTHREADS, SMEM_BYTES>>>(
        (const float*)d_in[0], (const float*)d_in[1], (const float*)d_in[2],
        (const float*)d_in[3], (const float*)d_in[4],
        (const float*)d_in[5], (const float*)d_in[6],
        (const float*)d_in[7], (const float*)d_in[8],
        (const float*)d_in[9], (const float*)d_in[10], (const float*)d_in[11],
        (float*)d_out);
}

// round 6
// speedup vs baseline: 1.1335x; 1.1320x over previous
#include <cuda_runtime.h>

// PLE layers, round 6: fused tf32 MMA kernel with cp.async W-ring pipeline.
//   - prepass kernel RN-converts all W banks into __device__ scratch (tf32 bits)
//   - main kernel: X tiles cp.async'd as raw fp32 (HMMA truncates to tf32),
//     W chunks cp.async'd from pre-converted scratch, 4-stage ring,
//     ONE __syncthreads per 32-K chunk, fragment regs double-buffered.

#define BT      16384
#define IN_D    256
#define EXP_D   128
#define NE      8
#define TB      64          // batch rows per CTA
#define KC      32          // K chunk
#define NBUF    4           // W smem ring depth
#define XSS     260         // x smem stride (words): bank = 4*gid+tig, conflict-free
#define WSS     136         // w smem stride (words): bank = 8*tig+gid, conflict-free
#define GSS     57          // gate-weight smem stride
#define NTHREADS 256
#define WSTK    (NE*IN_D*EXP_D)   // floats per W stack = 262144

__device__ float Wc_scratch[3 * WSTK];   // RN-tf32-converted W banks (3.1 MB)

__device__ __forceinline__ unsigned f2tf(float f) {
    unsigned u;
    asm("cvt.rna.tf32.f32 %0, %1;" : "=r"(u) : "f"(f));
    return u;
}

__device__ __forceinline__ void cp16(float* smem_dst, const float* gsrc) {
    unsigned d = (unsigned)__cvta_generic_to_shared(smem_dst);
    asm volatile("cp.async.cg.shared.global [%0], [%1], 16;\n" :: "r"(d), "l"(gsrc));
}
__device__ __forceinline__ void cp_commit() {
    asm volatile("cp.async.commit_group;\n");
}
template<int N> __device__ __forceinline__ void cp_wait() {
    asm volatile("cp.async.wait_group %0;\n" :: "n"(N));
}

__device__ __forceinline__ void mma8(float& c0, float& c1, float& c2, float& c3,
                                     unsigned a0, unsigned a1, unsigned a2, unsigned a3,
                                     unsigned b0, unsigned b1) {
    asm volatile(
        "mma.sync.aligned.m16n8k8.row.col.f32.tf32.tf32.f32 "
        "{%0,%1,%2,%3}, {%4,%5,%6,%7}, {%8,%9}, {%0,%1,%2,%3};\n"
        : "+f"(c0), "+f"(c1), "+f"(c2), "+f"(c3)
        : "r"(a0), "r"(a1), "r"(a2), "r"(a3), "r"(b0), "r"(b1));
}

// ---------------- prepass: RN-convert W banks to tf32 bits ----------------
__global__ void w_convert_kernel(const float* __restrict__ Wa,
                                 const float* __restrict__ Wb,
                                 const float* __restrict__ Wsx) {
    int i4 = blockIdx.x * blockDim.x + threadIdx.x;     // one float4 per thread
    int s  = i4 / (WSTK / 4);
    int o4 = i4 - s * (WSTK / 4);
    const float* src = (s == 0) ? Wa : (s == 1) ? Wb : Wsx;
    float4 v = __ldg((const float4*)src + o4);
    uint4 u;
    u.x = f2tf(v.x); u.y = f2tf(v.y); u.z = f2tf(v.z); u.w = f2tf(v.w);
    *((uint4*)(Wc_scratch + (size_t)s * WSTK) + o4) = u;
}

// ---------------- main fused kernel ----------------
__global__ __launch_bounds__(NTHREADS, 1)
void ple_kernel(const float* __restrict__ xa, const float* __restrict__ xb,
                const float* __restrict__ xsh,
                const float* __restrict__ ba, const float* __restrict__ bb,
                const float* __restrict__ bsx,
                const float* __restrict__ Ga, const float* __restrict__ Gb,
                const float* __restrict__ Gq,
                float* __restrict__ out)
{
    extern __shared__ float smem[];
    float* xs  = smem;                       // TB*XSS : x tile (raw fp32 bits)
    float* ws  = xs + TB * XSS;              // NBUF*KC*WSS : W ring (tf32 bits)
    float* wsm = ws + NBUF * KC * WSS;       // TB*GSS : gate weights
    float* bsm = wsm + TB * GSS;             // 3*1024 : biases

    const int tid  = threadIdx.x;
    const int lane = tid & 31;
    const int wid  = tid >> 5;
    const int gid  = lane >> 2;
    const int tig  = lane & 3;
    const int wm   = wid >> 2;               // 0..1
    const int wn   = wid & 3;                // 0..3
    const int row0 = blockIdx.x * TB;

    for (int i = tid; i < 1024; i += NTHREADS) {
        bsm[i]        = __ldg(ba + i);
        bsm[1024 + i] = __ldg(bb + i);
        bsm[2048 + i] = __ldg(bsx + i);
    }

    // X tile loader: 64 rows x 64 float4 = 4096 segments, 16 per thread
    auto issue_x = [&](const float* X) {
        const float* src = X + (size_t)row0 * IN_D;
        #pragma unroll
        for (int j = 0; j < 16; ++j) {
            int idx = tid + j * NTHREADS;
            int r = idx >> 6, s4 = (idx & 63) << 2;
            cp16(xs + r * XSS + s4, src + r * IN_D + s4);
        }
        cp_commit();
    };

    // ---------------- Phase 1: gate logits + softmax (full fp32) ----------------
    #pragma unroll 1
    for (int sg = 0; sg < 3; ++sg) {
        const float* X = (sg == 0) ? xa : (sg == 1) ? xb : xsh;
        const float* G = (sg == 0) ? Ga : (sg == 1) ? Gb : Gq;
        const int NG   = (sg == 2) ? 24 : 16;
        const int WOFF = sg * 16;

        __syncthreads();
        issue_x(X);
        cp_wait<0>();
        __syncthreads();

        for (int idx = tid; idx < TB * NG; idx += NTHREADS) {
            int r = idx / NG, g = idx - r * NG;
            const float4* xp = (const float4*)(xs + r * XSS);
            const float4* gp = (const float4*)(G + (size_t)g * IN_D);
            float acc = 0.f;
            #pragma unroll 8
            for (int k = 0; k < IN_D / 4; ++k) {
                float4 xv = xp[k];
                float4 gv = __ldg(gp + k);
                acc += xv.x * gv.x; acc += xv.y * gv.y;
                acc += xv.z * gv.z; acc += xv.w * gv.w;
            }
            wsm[r * GSS + WOFF + g] = acc;
        }
        __syncthreads();

        if (tid < TB) {
            float* wr = wsm + tid * GSS + WOFF;
            float m = wr[0];
            for (int g = 1; g < NG; ++g) m = fmaxf(m, wr[g]);
            float s = 0.f;
            for (int g = 0; g < NG; ++g) { float e = expf(wr[g] - m); wr[g] = e; s += e; }
            float inv = 1.f / s;
            for (int g = 0; g < NG; ++g) wr[g] *= inv;
        }
    }

    // ---------------- Phase 2: expert GEMMs + gated fold ----------------
    float oa[2][4][4] = {}, ob[2][4][4] = {}, os[2][4][4] = {};

    #pragma unroll 1
    for (int sg = 0; sg < 3; ++sg) {
        const float* X  = (sg == 0) ? xa : (sg == 1) ? xb : xsh;
        const float* Wg = Wc_scratch + (size_t)sg * WSTK;

        // W chunk q (q = e*8 + c): 32 rows x 32 float4 = 1024 segs, 4 per thread
        auto issue_chunk = [&](int q) {
            const float* src = Wg + (size_t)(q >> 3) * IN_D * EXP_D
                                  + (q & 7) * KC * EXP_D;
            float* dst = ws + (q & (NBUF - 1)) * (KC * WSS);
            #pragma unroll
            for (int j = 0; j < 4; ++j) {
                int idx = tid + j * NTHREADS;
                int r = idx >> 5, s4 = (idx & 31) << 2;
                cp16(dst + r * WSS + s4, src + r * EXP_D + s4);
            }
            cp_commit();
        };

        __syncthreads();               // all previous xs/ws readers done
        issue_x(X);                    // group: X tile
        issue_chunk(0);                // group: chunk 0
        issue_chunk(1);                // group: chunk 1

        float ec[2][4][4] = {};
        unsigned fa[2][8], fb[2][8];

        #pragma unroll 1
        for (int q = 0; q < 64; ++q) {
            const int c = q & 7;                      // chunk within expert
            if (q + 2 < 64) issue_chunk(q + 2);
            if (q < 62)      cp_wait<2>();
            else if (q == 62) cp_wait<1>();
            else              cp_wait<0>();
            __syncthreads();

            if (c == 0) {
                #pragma unroll
                for (int mt = 0; mt < 2; ++mt)
                    #pragma unroll
                    for (int nt = 0; nt < 4; ++nt)
                        #pragma unroll
                        for (int v = 0; v < 4; ++v) ec[mt][nt][v] = 0.f;
            }

            const float* wb = ws + (q & (NBUF - 1)) * (KC * WSS);

            // preload k-step 0 fragments
            #pragma unroll
            for (int mt = 0; mt < 2; ++mt) {
                const float* xr = xs + (wm * 32 + mt * 16 + gid) * XSS + c * KC;
                fa[0][mt * 4 + 0] = __float_as_uint(xr[tig]);
                fa[0][mt * 4 + 1] = __float_as_uint(xr[8 * XSS + tig]);
                fa[0][mt * 4 + 2] = __float_as_uint(xr[tig + 4]);
                fa[0][mt * 4 + 3] = __float_as_uint(xr[8 * XSS + tig + 4]);
            }
            #pragma unroll
            for (int nt = 0; nt < 4; ++nt) {
                int n = wn * 32 + nt * 8 + gid;
                fb[0][nt * 2 + 0] = __float_as_uint(wb[tig * WSS + n]);
                fb[0][nt * 2 + 1] = __float_as_uint(wb[(tig + 4) * WSS + n]);
            }

            #pragma unroll
            for (int kk = 0; kk < KC / 8; ++kk) {
                const int cur = kk & 1, nxt = cur ^ 1;
                if (kk < KC / 8 - 1) {  // prefetch next k-step fragments
                    int kb = c * KC + (kk + 1) * 8;
                    #pragma unroll
                    for (int mt = 0; mt < 2; ++mt) {
                        const float* xr = xs + (wm * 32 + mt * 16 + gid) * XSS + kb;
                        fa[nxt][mt * 4 + 0] = __float_as_uint(xr[tig]);
                        fa[nxt][mt * 4 + 1] = __float_as_uint(xr[8 * XSS + tig]);
                        fa[nxt][mt * 4 + 2] = __float_as_uint(xr[tig + 4]);
                        fa[nxt][mt * 4 + 3] = __float_as_uint(xr[8 * XSS + tig + 4]);
                    }
                    #pragma unroll
                    for (int nt = 0; nt < 4; ++nt) {
                        int n = wn * 32 + nt * 8 + gid;
                        fb[nxt][nt * 2 + 0] = __float_as_uint(wb[((kk + 1) * 8 + tig) * WSS + n]);
                        fb[nxt][nt * 2 + 1] = __float_as_uint(wb[((kk + 1) * 8 + tig + 4) * WSS + n]);
                    }
                }
                #pragma unroll
                for (int nt = 0; nt < 4; ++nt)
                    #pragma unroll
                    for (int mt = 0; mt < 2; ++mt)
                        mma8(ec[mt][nt][0], ec[mt][nt][1], ec[mt][nt][2], ec[mt][nt][3],
                             fa[cur][mt * 4 + 0], fa[cur][mt * 4 + 1],
                             fa[cur][mt * 4 + 2], fa[cur][mt * 4 + 3],
                             fb[cur][nt * 2 + 0], fb[cur][nt * 2 + 1]);
            }

            if (c == 7) {
                // fold expert e = q>>3 into gated output accumulators
                const int e = q >> 3;
                #pragma unroll
                for (int mt = 0; mt < 2; ++mt) {
                    int rl = wm * 32 + mt * 16 + gid;
                    float w1l, w1h, w2l, w2h, w3l = 0.f, w3h = 0.f;
                    if (sg == 0) {
                        w1l = wsm[rl * GSS + e];      w1h = wsm[(rl + 8) * GSS + e];
                        w2l = wsm[rl * GSS + 32 + e]; w2h = wsm[(rl + 8) * GSS + 32 + e];
                    } else if (sg == 1) {
                        w1l = wsm[rl * GSS + 16 + e]; w1h = wsm[(rl + 8) * GSS + 16 + e];
                        w2l = wsm[rl * GSS + 40 + e]; w2h = wsm[(rl + 8) * GSS + 40 + e];
                    } else {
                        w1l = wsm[rl * GSS + 8 + e];  w1h = wsm[(rl + 8) * GSS + 8 + e];
                        w2l = wsm[rl * GSS + 24 + e]; w2h = wsm[(rl + 8) * GSS + 24 + e];
                        w3l = wsm[rl * GSS + 48 + e]; w3h = wsm[(rl + 8) * GSS + 48 + e];
                    }
                    #pragma unroll
                    for (int nt = 0; nt < 4; ++nt) {
                        int c0 = wn * 32 + nt * 8 + 2 * tig;
                        const float* bp = bsm + sg * 1024 + e * EXP_D + c0;
                        float t0 = ec[mt][nt][0] + bp[0];
                        float t1 = ec[mt][nt][1] + bp[1];
                        float t2 = ec[mt][nt][2] + bp[0];
                        float t3 = ec[mt][nt][3] + bp[1];
                        if (sg == 0) {
                            oa[mt][nt][0] += w1l * t0; oa[mt][nt][1] += w1l * t1;
                            oa[mt][nt][2] += w1h * t2; oa[mt][nt][3] += w1h * t3;
                            os[mt][nt][0] += w2l * t0; os[mt][nt][1] += w2l * t1;
                            os[mt][nt][2] += w2h * t2; os[mt][nt][3] += w2h * t3;
                        } else if (sg == 1) {
                            ob[mt][nt][0] += w1l * t0; ob[mt][nt][1] += w1l * t1;
                            ob[mt][nt][2] += w1h * t2; ob[mt][nt][3] += w1h * t3;
                            os[mt][nt][0] += w2l * t0; os[mt][nt][1] += w2l * t1;
                            os[mt][nt][2] += w2h * t2; os[mt][nt][3] += w2h * t3;
                        } else {
                            oa[mt][nt][0] += w1l * t0; oa[mt][nt][1] += w1l * t1;
                            oa[mt][nt][2] += w1h * t2; oa[mt][nt][3] += w1h * t3;
                            ob[mt][nt][0] += w2l * t0; ob[mt][nt][1] += w2l * t1;
                            ob[mt][nt][2] += w2h * t2; ob[mt][nt][3] += w2h * t3;
                            os[mt][nt][0] += w3l * t0; os[mt][nt][1] += w3l * t1;
                            os[mt][nt][2] += w3h * t2; os[mt][nt][3] += w3h * t3;
                        }
                    }
                }
            }
        }
    }

    // ---------------- write out: [out_a | out_b | out_s], each [B,128] ----------------
    const size_t OS = (size_t)BT * EXP_D;
    #pragma unroll
    for (int mt = 0; mt < 2; ++mt) {
        int r = row0 + wm * 32 + mt * 16 + gid;
        #pragma unroll
        for (int nt = 0; nt < 4; ++nt) {
            int c0 = wn * 32 + nt * 8 + 2 * tig;
            size_t p0 = (size_t)r * EXP_D + c0;
            size_t p1 = (size_t)(r + 8) * EXP_D + c0;
            *(float2*)(out + p0)          = make_float2(oa[mt][nt][0], oa[mt][nt][1]);
            *(float2*)(out + p1)          = make_float2(oa[mt][nt][2], oa[mt][nt][3]);
            *(float2*)(out + OS + p0)     = make_float2(ob[mt][nt][0], ob[mt][nt][1]);
            *(float2*)(out + OS + p1)     = make_float2(ob[mt][nt][2], ob[mt][nt][3]);
            *(float2*)(out + 2 * OS + p0) = make_float2(os[mt][nt][0], os[mt][nt][1]);
            *(float2*)(out + 2 * OS + p1) = make_float2(os[mt][nt][2], os[mt][nt][3]);
        }
    }
}

extern "C" void kernel_launch(void* const* d_in, const int* in_sizes, int n_in,
                              void* d_out, int out_size) {
    (void)in_sizes; (void)n_in; (void)out_size;

    // prepass: RN tf32 conversion of W banks (3*262144 floats, 1 float4/thread)
    w_convert_kernel<<<3 * WSTK / 4 / NTHREADS, NTHREADS>>>(
        (const float*)d_in[3], (const float*)d_in[5], (const float*)d_in[7]);

    constexpr int SMEM_BYTES =
        (TB * XSS + NBUF * KC * WSS + TB * GSS + 3 * 1024) * 4;   // 163,072 B
    cudaFuncSetAttribute(ple_kernel, cudaFuncAttributeMaxDynamicSharedMemorySize, SMEM_BYTES);
    ple_kernel<<<BT / TB, NTHREADS, SMEM_BYTES>>>(
        (const float*)d_in[0], (const float*)d_in[1], (const float*)d_in[2],
        (const float*)d_in[4], (const float*)d_in[6], (const float*)d_in[8],
        (const float*)d_in[9], (const float*)d_in[10], (const float*)d_in[11],
        (float*)d_out);
}